// round 15
// baseline (speedup 1.0000x reference)
#include <cuda_runtime.h>
#include <cuda_fp16.h>
#include <cstdint>

// ---------------------------------------------------------------------------
// SimplifiedHAttention — closed form + XLA-tree Z (R7) + tensor-core GEMMs.
// R15: fp16 asymmetric 2-product split (A = Ah+Al fp16 [22-bit], W single
// fp16 [11-bit]):  A@W ~= Ah@Wh + Al@Wh   — 2 mma per tile instead of 3.
// Rationale: R8/R13/R14 all pinned GEMM at ~84.6us / ~52% tensor across very
// different configs => legacy mma.sync time scales ONLY with mma count.
// Error budget: W-rounding 1.4e-4/GEMM, ~2e-4 total (5x margin vs 1e-3).
// Scan chain: R13 structure (measured faster than R14 fusion).
// ---------------------------------------------------------------------------

#define B_ 2
#define S_ 2048
#define E_ 1024
#define H_ 16
#define TS 128
#define NT (S_ / TS)
#define M_ (B_ * S_)        // 4096 GEMM rows
#define GK E_               // 1024 GEMM K
#define TLD 40              // smem row stride in fp16 (80B, ldmatrix conflict-free)

static_assert(S_ % TS == 0, "tile");

__device__ float g_vm [(size_t)B_ * S_ * E_];
__device__ float g_pre[(size_t)B_ * S_ * E_];
__device__ float g_suf[(size_t)B_ * S_ * E_];
__device__ float g_tsum [(size_t)B_ * NT * E_];
__device__ float g_tofff[(size_t)B_ * NT * E_];
__device__ float g_toffb[(size_t)B_ * NT * E_];
__device__ float4 g_wts[(size_t)B_ * H_ * S_];
__device__ __half g_xh [(size_t)M_ * E_];
__device__ __half g_xl [(size_t)M_ * E_];
__device__ __half g_ath[(size_t)M_ * E_];
__device__ __half g_atl[(size_t)M_ * E_];
__device__ __half g_wvh[(size_t)E_ * E_];
__device__ __half g_woh[(size_t)E_ * E_];

// ---------------------------------------------------------------------------
// fp16 hi/lo split + single conversion
// ---------------------------------------------------------------------------
__device__ __forceinline__ void split_fp16(float a, __half& hi, __half& lo)
{
    hi = __float2half_rn(a);
    lo = __float2half_rn(__fadd_rn(a, -__half2float(hi)));
}

__global__ __launch_bounds__(256)
void split2_kernel(const float* __restrict__ src, __half* __restrict__ hi,
                   __half* __restrict__ lo, int n4)
{
    int i = blockIdx.x * 256 + threadIdx.x;
    if (i >= n4) return;
    float4 v = ((const float4*)src)[i];
    __half h0,h1,h2,h3,l0,l1,l2,l3;
    split_fp16(v.x,h0,l0); split_fp16(v.y,h1,l1);
    split_fp16(v.z,h2,l2); split_fp16(v.w,h3,l3);
    ((ushort4*)hi)[i] = make_ushort4(__half_as_ushort(h0), __half_as_ushort(h1),
                                     __half_as_ushort(h2), __half_as_ushort(h3));
    ((ushort4*)lo)[i] = make_ushort4(__half_as_ushort(l0), __half_as_ushort(l1),
                                     __half_as_ushort(l2), __half_as_ushort(l3));
}

__global__ __launch_bounds__(256)
void cvt16_kernel(const float* __restrict__ src, __half* __restrict__ hi, int n4)
{
    int i = blockIdx.x * 256 + threadIdx.x;
    if (i >= n4) return;
    float4 v = ((const float4*)src)[i];
    ((ushort4*)hi)[i] = make_ushort4(__half_as_ushort(__float2half_rn(v.x)),
                                     __half_as_ushort(__float2half_rn(v.y)),
                                     __half_as_ushort(__float2half_rn(v.z)),
                                     __half_as_ushort(__float2half_rn(v.w)));
}

// ---------------------------------------------------------------------------
// GEMM helpers (baseline ISA: cp.async, ldmatrix, mma.sync fp16)
// ---------------------------------------------------------------------------
__device__ __forceinline__ void cpasync16(uint32_t saddr, const void* src)
{
    asm volatile("cp.async.cg.shared.global [%0], [%1], 16;" :: "r"(saddr), "l"(src));
}

__device__ __forceinline__ void ldsm_x4(uint32_t* r, uint32_t saddr)
{
    asm volatile("ldmatrix.sync.aligned.m8n8.x4.shared.b16 {%0,%1,%2,%3}, [%4];"
        : "=r"(r[0]), "=r"(r[1]), "=r"(r[2]), "=r"(r[3]) : "r"(saddr));
}

__device__ __forceinline__ void mma_fp16(float* c, const uint32_t* a, const uint32_t* b)
{
    asm volatile(
        "mma.sync.aligned.m16n8k16.row.col.f32.f16.f16.f32 "
        "{%0,%1,%2,%3}, {%4,%5,%6,%7}, {%8,%9}, {%0,%1,%2,%3};\n"
        : "+f"(c[0]), "+f"(c[1]), "+f"(c[2]), "+f"(c[3])
        : "r"(a[0]), "r"(a[1]), "r"(a[2]), "r"(a[3]), "r"(b[0]), "r"(b[1]));
}

// Stage layout (fp16 units), uniform row stride TLD:
//   rows [0,128)   Ah    rows [128,256) Al    rows [256,512) Wh (256 cols)
#define ROWS_STG 512
#define OFF_AL (128 * TLD)
#define OFF_WH (256 * TLD)
#define STAGE_FP16 (ROWS_STG * TLD)        // 20480
#define STAGE_BYTES (STAGE_FP16 * 2)       // 40960
#define GSMEM_BYTES (2 * STAGE_BYTES)      // 81920

// ---------------------------------------------------------------------------
// 2-product fp16 GEMM: C[m,n] = rowmask(m)*(sum_k A[m,k]W[n,k] + bias[n])
// 128x256 block, 8 warps (2m x 4n), warp tile 64x64, BK=32, double buffer,
// one __syncthreads per K-iter, ldmatrix.x4 fragments. Grid = single wave.
// ---------------------------------------------------------------------------
__global__ __launch_bounds__(256)
void gemm_split_kernel(const __half* __restrict__ Ah,
                       const __half* __restrict__ Al,
                       const __half* __restrict__ Wh,
                       const float* __restrict__ bias,
                       const int* __restrict__ mask,
                       float* __restrict__ C)
{
    extern __shared__ __half sm[];
    const uint32_t sm32 = (uint32_t)__cvta_generic_to_shared(sm);

    const int tid  = threadIdx.x;
    const int lane = tid & 31;
    const int w    = tid >> 5;
    const int wm   = w >> 2;           // 0..1  (64 rows each)
    const int wn   = w & 3;            // 0..3  (64 cols each)
    const int row0 = blockIdx.y * 128;
    const int col0 = blockIdx.x * 256;
    const int lr   = lane >> 2;        // 0..7
    const int lq   = (lane & 3) << 1;  // 0,2,4,6

    // ldmatrix lane-address bases (bytes) — mapping validated R13/R14.
    const int amat = lane >> 3, arow = lane & 7;
    const uint32_t aoff = (uint32_t)(((wm * 64 + (amat & 1) * 8 + arow) * TLD
                                      + (amat >> 1) * 8) * 2);
    const uint32_t boff = (uint32_t)(((wn * 64 + (amat >> 1) * 8 + arow) * TLD
                                      + (amat & 1) * 8) * 2);

    float acc[4][8][4];
    #pragma unroll
    for (int ms = 0; ms < 4; ms++)
        #pragma unroll
        for (int ns = 0; ns < 8; ns++)
            #pragma unroll
            for (int t = 0; t < 4; t++) acc[ms][ns][t] = 0.0f;

    // 8 cp.async per thread per stage (512 rows x 4 16B-chunks / 256 thr).
    #define COPY_STAGE(stg, kbase) do {                                        \
        uint32_t sb = sm32 + (uint32_t)((stg) * STAGE_BYTES);                  \
        _Pragma("unroll")                                                      \
        for (int i = 0; i < 8; i++) {                                          \
            int f  = tid + i * 256;                                            \
            int r  = f >> 2;                                                   \
            int cq = (f & 3) << 3;                                             \
            const __half* g; int grow;                                        \
            if (r < 128)      { g = Ah; grow = row0 + r; }                     \
            else if (r < 256) { g = Al; grow = row0 + r - 128; }               \
            else              { g = Wh; grow = col0 + r - 256; }               \
            cpasync16(sb + (uint32_t)((r * TLD + cq) * 2),                     \
                      g + (size_t)grow * GK + (kbase) + cq);                   \
        }                                                                      \
    } while (0)

    COPY_STAGE(0, 0);
    asm volatile("cp.async.commit_group;");

    const int NITER = GK / 32;     // 32
    for (int it = 0; it < NITER; it++) {
        asm volatile("cp.async.wait_group 0;");
        __syncthreads();           // publishes stage it, guards buf (it+1)&1 reuse
        if (it + 1 < NITER) COPY_STAGE((it + 1) & 1, (it + 1) * 32);
        asm volatile("cp.async.commit_group;");

        const uint32_t sb = sm32 + (uint32_t)((it & 1) * STAGE_BYTES);
        #pragma unroll
        for (int kk = 0; kk < 32; kk += 16) {
            const uint32_t kb = (uint32_t)(kk * 2);
            uint32_t bh[4][4];
            #pragma unroll
            for (int p = 0; p < 4; p++) {
                uint32_t ba = sb + (uint32_t)(OFF_WH * 2) + boff
                            + (uint32_t)(p * 16 * TLD * 2) + kb;
                ldsm_x4(bh[p], ba);
            }
            #pragma unroll
            for (int ms = 0; ms < 4; ms++) {
                uint32_t aa = sb + aoff + (uint32_t)(ms * 16 * TLD * 2) + kb;
                uint32_t ah[4], al[4];
                ldsm_x4(ah, aa);
                ldsm_x4(al, aa + (uint32_t)(OFF_AL * 2));
                #pragma unroll
                for (int ns = 0; ns < 8; ns++) {
                    const uint32_t* bhp = &bh[ns >> 1][(ns & 1) * 2];
                    mma_fp16(acc[ms][ns], ah, bhp);
                    mma_fp16(acc[ms][ns], al, bhp);
                }
            }
        }
    }

    // Epilogue: bias + optional row mask.
    #pragma unroll
    for (int ms = 0; ms < 4; ms++) {
        int r = row0 + wm * 64 + ms * 16 + lr;
        float m0 = mask ? (float)mask[r]     : 1.0f;
        float m1 = mask ? (float)mask[r + 8] : 1.0f;
        #pragma unroll
        for (int ns = 0; ns < 8; ns++) {
            int c = col0 + wn * 64 + ns * 8 + lq;
            float b0 = bias[c], b1 = bias[c + 1];
            float2 o0 = make_float2(m0 * (acc[ms][ns][0] + b0),
                                    m0 * (acc[ms][ns][1] + b1));
            float2 o1 = make_float2(m1 * (acc[ms][ns][2] + b0),
                                    m1 * (acc[ms][ns][3] + b1));
            *(float2*)(C + (size_t)r * E_ + c)       = o0;
            *(float2*)(C + (size_t)(r + 8) * E_ + c) = o1;
        }
    }
}

// ---------------------------------------------------------------------------
// K2: within-tile fwd-exclusive prefix + bwd-inclusive suffix along S.
// ---------------------------------------------------------------------------
__global__ __launch_bounds__(256)
void scan_local_kernel(const float* __restrict__ vm, float* __restrict__ pre,
                       float* __restrict__ suf, float* __restrict__ tsum)
{
    int e = blockIdx.x * 256 + threadIdx.x;
    int t = blockIdx.y;
    int b = blockIdx.z;
    size_t cbase = ((size_t)b * S_ + (size_t)t * TS) * E_ + e;
    const float* src = vm + cbase;
    float* pdst = pre + cbase;
    float* sdst = suf + cbase;

    float acc = 0.0f;
    #pragma unroll 8
    for (int s = 0; s < TS; s++) {
        float v = src[(size_t)s * E_];
        pdst[(size_t)s * E_] = acc;
        acc += v;
    }
    tsum[((size_t)b * NT + t) * E_ + e] = acc;

    acc = 0.0f;
    #pragma unroll 8
    for (int s = TS - 1; s >= 0; s--) {
        float v = src[(size_t)s * E_];
        acc += v;
        sdst[(size_t)s * E_] = acc;
    }
}

// ---------------------------------------------------------------------------
// K3: cross-tile fwd/bwd offsets.
// ---------------------------------------------------------------------------
__global__ __launch_bounds__(256)
void scan_tiles_kernel(const float* __restrict__ tsum,
                       float* __restrict__ toff_f, float* __restrict__ toff_b)
{
    int e = blockIdx.x * 256 + threadIdx.x;
    int b = blockIdx.y;
    float ts[NT];
    #pragma unroll
    for (int t = 0; t < NT; t++)
        ts[t] = tsum[((size_t)b * NT + t) * E_ + e];
    float acc = 0.0f;
    #pragma unroll
    for (int t = 0; t < NT; t++) {
        toff_f[((size_t)b * NT + t) * E_ + e] = acc;
        acc += ts[t];
    }
    acc = 0.0f;
    #pragma unroll
    for (int t = NT - 1; t >= 0; t--) {
        toff_b[((size_t)b * NT + t) * E_ + e] = acc;
        acc += ts[t];
    }
}

// ---------------------------------------------------------------------------
// K_w: per-(b,h,i) weights, Z in XLA:GPU row-reduce order (R7-validated —
// do not touch).
// ---------------------------------------------------------------------------
__device__ __forceinline__ float wval(int j, int i, int odd,
                                      float c0, float c1, float c2)
{
    if (j >= i) return c0;
    if (odd && j == i - 1) return c1;
    return c2;
}

__global__ __launch_bounds__(256)
void weights_kernel(const float* __restrict__ hier, float4* __restrict__ wts)
{
    int i = blockIdx.x * 256 + threadIdx.x;
    int h = blockIdx.y;
    int b = blockIdx.z;
    const float* hp = hier + ((size_t)b * H_ + h) * 3;
    float c0 = hp[0];
    float c1 = __fmul_rn(0.5f,  hp[1]);
    float c2 = __fmul_rn(0.25f, hp[2]);
    int odd = i & 1;

    float r[32];
    #pragma unroll 1
    for (int w = 0; w < 32; w++) {
        int jlo = w << 6;
        int jhi = jlo + 63;
        if (jlo >= i) {
            r[w] = __fmul_rn(64.0f, c0);
        } else if (jhi < i && !(odd && (i - 1) <= jhi)) {
            r[w] = __fmul_rn(64.0f, c2);
        } else {
            float p[32];
            #pragma unroll
            for (int t = 0; t < 32; t++) {
                int j = jlo + 2 * t;
                p[t] = __fadd_rn(wval(j, i, odd, c0, c1, c2),
                                 wval(j + 1, i, odd, c0, c1, c2));
            }
            #pragma unroll
            for (int s = 16; s > 0; s >>= 1)
                #pragma unroll
                for (int l = 0; l < 16; l++)
                    if (l < s) p[l] = __fadd_rn(p[l], p[l + s]);
            r[w] = p[0];
        }
    }
    #pragma unroll
    for (int s = 16; s > 0; s >>= 1)
        #pragma unroll
        for (int l = 0; l < 16; l++)
            if (l < s) r[l] = __fadd_rn(r[l], r[l + s]);

    float Z = __fadd_rn(r[0], 1e-8f);
    float4 o;
    o.x = __fdiv_rn(c0, Z);
    o.y = __fdiv_rn(c1, Z);
    o.z = __fdiv_rn(c2, Z);
    o.w = 0.0f;
    wts[((size_t)b * H_ + h) * S_ + i] = o;
}

// ---------------------------------------------------------------------------
// K4: combine; emits att as fp16 hi/lo split (K5 GEMM A-operand).
// ---------------------------------------------------------------------------
__global__ __launch_bounds__(256)
void combine_kernel(const float* __restrict__ pre, const float* __restrict__ suf,
                    const float* __restrict__ toff_f, const float* __restrict__ toff_b,
                    const float* __restrict__ vm, const float4* __restrict__ wts,
                    __half* __restrict__ atth, __half* __restrict__ attl)
{
    int i = blockIdx.x;
    int b = blockIdx.y;
    int odd = i & 1;
    int t = i >> 7;                                   // TS = 128

    #pragma unroll
    for (int c = 0; c < E_ / 256; c++) {
        int e = threadIdx.x + c * 256;
        int h = e >> 6;                               // dh = 64
        float4 w = wts[((size_t)b * H_ + h) * S_ + i];

        size_t base = ((size_t)b * S_ + i) * E_ + e;
        size_t tidx = ((size_t)b * NT + t) * E_ + e;
        float p  = pre[base] + toff_f[tidx];
        float sf = suf[base] + toff_b[tidx];
        float edge = odd ? vm[base - E_] : 0.0f;
        float val = w.x * sf + w.y * edge + w.z * (p - edge);
        __half hi, lo;
        split_fp16(val, hi, lo);
        atth[base] = hi;
        attl[base] = lo;
    }
}

// ---------------------------------------------------------------------------
// Launch. Inputs (metadata order):
// 0:x 1:attention_mask 2:level_indices(unused) 3:Wq 4:bq 5:Wk 6:bk
// 7:Wv 8:bv 9:hier 10:Wo 11:bo
// ---------------------------------------------------------------------------
extern "C" void kernel_launch(void* const* d_in, const int* in_sizes, int n_in,
                              void* d_out, int out_size)
{
    const float* x    = (const float*)d_in[0];
    const int*   am   = (const int*)  d_in[1];
    const float* Wv   = (const float*)d_in[7];
    const float* bv   = (const float*)d_in[8];
    const float* hier = (const float*)d_in[9];
    const float* Wo   = (const float*)d_in[10];
    const float* bo   = (const float*)d_in[11];
    float* out = (float*)d_out;

    float *vm, *pre, *suf, *tsum, *toff_f, *toff_b;
    float4* wts;
    __half *xh, *xl, *ath, *atl, *wvh, *woh;
    cudaGetSymbolAddress((void**)&vm,     g_vm);
    cudaGetSymbolAddress((void**)&pre,    g_pre);
    cudaGetSymbolAddress((void**)&suf,    g_suf);
    cudaGetSymbolAddress((void**)&tsum,   g_tsum);
    cudaGetSymbolAddress((void**)&toff_f, g_tofff);
    cudaGetSymbolAddress((void**)&toff_b, g_toffb);
    cudaGetSymbolAddress((void**)&wts,    g_wts);
    cudaGetSymbolAddress((void**)&xh,     g_xh);
    cudaGetSymbolAddress((void**)&xl,     g_xl);
    cudaGetSymbolAddress((void**)&ath,    g_ath);
    cudaGetSymbolAddress((void**)&atl,    g_atl);
    cudaGetSymbolAddress((void**)&wvh,    g_wvh);
    cudaGetSymbolAddress((void**)&woh,    g_woh);

    static int smem_set = 0;
    if (!smem_set) {
        cudaFuncSetAttribute(gemm_split_kernel,
                             cudaFuncAttributeMaxDynamicSharedMemorySize,
                             GSMEM_BYTES);
        smem_set = 1;
    }

    // Prep: x -> fp16 hi/lo; Wv, Wo -> fp16 (single)
    split2_kernel<<<(M_ * E_ / 4 + 255) / 256, 256>>>(x,  xh,  xl, M_ * E_ / 4);
    cvt16_kernel<<<(E_ * E_ / 4 + 255) / 256, 256>>>(Wv, wvh, E_ * E_ / 4);
    cvt16_kernel<<<(E_ * E_ / 4 + 255) / 256, 256>>>(Wo, woh, E_ * E_ / 4);

    dim3 gemm_grid(E_ / 256, M_ / 128);   // (4, 32) = 128 CTAs, single wave

    // K1: vm = mask * (x @ Wv^T + bv)
    gemm_split_kernel<<<gemm_grid, 256, GSMEM_BYTES>>>(xh, xl, wvh, bv, am, vm);

    // K_w: weights with XLA-tree Z
    weights_kernel<<<dim3(S_ / 256, H_, B_), 256>>>(hier, wts);

    // K2/K3: hierarchical fwd/bwd scans along S
    scan_local_kernel<<<dim3(E_ / 256, NT, B_), 256>>>(vm, pre, suf, tsum);
    scan_tiles_kernel<<<dim3(E_ / 256, B_), 256>>>(tsum, toff_f, toff_b);

    // K4: closed-form hierarchical attention -> att (fp16 hi/lo)
    combine_kernel<<<dim3(S_, B_), 256>>>(pre, suf, toff_f, toff_b, vm, wts, ath, atl);

    // K5: out = att @ Wo^T + bo
    gemm_split_kernel<<<gemm_grid, 256, GSMEM_BYTES>>>(ath, atl, woh, bo,
                                                       nullptr, out);
}

// round 16
// speedup vs baseline: 1.1674x; 1.1674x over previous
#include <cuda_runtime.h>
#include <cuda_bf16.h>
#include <cstdint>

// ---------------------------------------------------------------------------
// SimplifiedHAttention — closed form + XLA-tree Z (R7) + bf16 split-3 GEMMs
// on mma.sync (legacy pipe; tcgen05 unavailable at compute_103 target).
// R16: GEMM = R14 config verbatim (bf16 split-3, 84.6us floor — R8/R13/R14
// invariant; f16 measured 1.6x worse per-instr in R15). Non-GEMM chain
// rebuilt: TS=32 fused scan+combine (4x parallelism, no pre/suf arrays).
// ---------------------------------------------------------------------------

#define B_ 2
#define S_ 2048
#define E_ 1024
#define H_ 16
#define TS2 32
#define NT2 (S_ / TS2)      // 64
#define M_ (B_ * S_)        // 4096 GEMM rows
#define GK E_               // 1024 GEMM K
#define TLD 40              // smem row stride in bf16 (80B, ldmatrix conflict-free)

__device__ float g_vm [(size_t)B_ * S_ * E_];
__device__ float g_tsum [(size_t)B_ * NT2 * E_];
__device__ float g_tofff[(size_t)B_ * NT2 * E_];
__device__ float g_toffb[(size_t)B_ * NT2 * E_];
__device__ float4 g_wts[(size_t)B_ * H_ * S_];
__device__ __nv_bfloat16 g_xh [(size_t)M_ * E_];
__device__ __nv_bfloat16 g_xl [(size_t)M_ * E_];
__device__ __nv_bfloat16 g_ath[(size_t)M_ * E_];
__device__ __nv_bfloat16 g_atl[(size_t)M_ * E_];
__device__ __nv_bfloat16 g_wvh[(size_t)E_ * E_];
__device__ __nv_bfloat16 g_wvl[(size_t)E_ * E_];
__device__ __nv_bfloat16 g_woh[(size_t)E_ * E_];
__device__ __nv_bfloat16 g_wol[(size_t)E_ * E_];

// ---------------------------------------------------------------------------
// hi/lo bf16 split
// ---------------------------------------------------------------------------
__device__ __forceinline__ void split_bf16(float a, __nv_bfloat16& hi, __nv_bfloat16& lo)
{
    hi = __float2bfloat16_rn(a);
    lo = __float2bfloat16_rn(__fadd_rn(a, -__bfloat162float(hi)));
}

__global__ __launch_bounds__(256)
void split_kernel(const float* __restrict__ src, __nv_bfloat16* __restrict__ hi,
                  __nv_bfloat16* __restrict__ lo, int n4)
{
    int i = blockIdx.x * 256 + threadIdx.x;
    if (i >= n4) return;
    float4 v = ((const float4*)src)[i];
    __nv_bfloat16 h0,h1,h2,h3,l0,l1,l2,l3;
    split_bf16(v.x,h0,l0); split_bf16(v.y,h1,l1);
    split_bf16(v.z,h2,l2); split_bf16(v.w,h3,l3);
    ((ushort4*)hi)[i] = make_ushort4(__bfloat16_as_ushort(h0), __bfloat16_as_ushort(h1),
                                     __bfloat16_as_ushort(h2), __bfloat16_as_ushort(h3));
    ((ushort4*)lo)[i] = make_ushort4(__bfloat16_as_ushort(l0), __bfloat16_as_ushort(l1),
                                     __bfloat16_as_ushort(l2), __bfloat16_as_ushort(l3));
}

// ---------------------------------------------------------------------------
// GEMM helpers (baseline ISA: cp.async, ldmatrix, mma.sync bf16)
// ---------------------------------------------------------------------------
__device__ __forceinline__ void cpasync16(uint32_t saddr, const void* src)
{
    asm volatile("cp.async.cg.shared.global [%0], [%1], 16;" :: "r"(saddr), "l"(src));
}

__device__ __forceinline__ void ldsm_x4(uint32_t* r, uint32_t saddr)
{
    asm volatile("ldmatrix.sync.aligned.m8n8.x4.shared.b16 {%0,%1,%2,%3}, [%4];"
        : "=r"(r[0]), "=r"(r[1]), "=r"(r[2]), "=r"(r[3]) : "r"(saddr));
}

__device__ __forceinline__ void mma_bf16(float* c, const uint32_t* a, const uint32_t* b)
{
    asm volatile(
        "mma.sync.aligned.m16n8k16.row.col.f32.bf16.bf16.f32 "
        "{%0,%1,%2,%3}, {%4,%5,%6,%7}, {%8,%9}, {%0,%1,%2,%3};\n"
        : "+f"(c[0]), "+f"(c[1]), "+f"(c[2]), "+f"(c[3])
        : "r"(a[0]), "r"(a[1]), "r"(a[2]), "r"(a[3]), "r"(b[0]), "r"(b[1]));
}

// Stage layout (bf16 units), uniform row stride TLD (R14-validated):
//   rows [0,128)   Ah    rows [128,256) Al
//   rows [256,512) Wh    rows [512,768) Wl
#define ROWS_STG 768
#define OFF_AL (128 * TLD)
#define OFF_WH (256 * TLD)
#define OFF_WL (512 * TLD)
#define STAGE_BF16 (ROWS_STG * TLD)        // 30720
#define STAGE_BYTES (STAGE_BF16 * 2)       // 61440
#define GSMEM_BYTES (2 * STAGE_BYTES)      // 122880

// ---------------------------------------------------------------------------
// Split-bf16 tensor GEMM (R14 verbatim): C = rowmask*(A@W^T + bias).
// 128x256 block, 8 warps (2m x 4n), warp tile 64x64, BK=32, double buffer,
// one __syncthreads per K-iter, ldmatrix.x4 fragments.
// ---------------------------------------------------------------------------
__global__ __launch_bounds__(256)
void gemm_split_kernel(const __nv_bfloat16* __restrict__ Ah,
                       const __nv_bfloat16* __restrict__ Al,
                       const __nv_bfloat16* __restrict__ Wh,
                       const __nv_bfloat16* __restrict__ Wl,
                       const float* __restrict__ bias,
                       const int* __restrict__ mask,
                       float* __restrict__ C)
{
    extern __shared__ __nv_bfloat16 sm[];
    const uint32_t sm32 = (uint32_t)__cvta_generic_to_shared(sm);

    const int tid  = threadIdx.x;
    const int lane = tid & 31;
    const int w    = tid >> 5;
    const int wm   = w >> 2;           // 0..1  (64 rows each)
    const int wn   = w & 3;            // 0..3  (64 cols each)
    const int row0 = blockIdx.y * 128;
    const int col0 = blockIdx.x * 256;
    const int lr   = lane >> 2;        // 0..7
    const int lq   = (lane & 3) << 1;  // 0,2,4,6

    const int amat = lane >> 3, arow = lane & 7;
    const uint32_t aoff = (uint32_t)(((wm * 64 + (amat & 1) * 8 + arow) * TLD
                                      + (amat >> 1) * 8) * 2);
    const uint32_t boff = (uint32_t)(((wn * 64 + (amat >> 1) * 8 + arow) * TLD
                                      + (amat & 1) * 8) * 2);

    float acc[4][8][4];
    #pragma unroll
    for (int ms = 0; ms < 4; ms++)
        #pragma unroll
        for (int ns = 0; ns < 8; ns++)
            #pragma unroll
            for (int t = 0; t < 4; t++) acc[ms][ns][t] = 0.0f;

    #define COPY_STAGE(stg, kbase) do {                                        \
        uint32_t sb = sm32 + (uint32_t)((stg) * STAGE_BYTES);                  \
        _Pragma("unroll")                                                      \
        for (int i = 0; i < 12; i++) {                                         \
            int f  = tid + i * 256;                                            \
            int r  = f >> 2;                                                   \
            int cq = (f & 3) << 3;                                             \
            const __nv_bfloat16* g; int grow;                                  \
            if (r < 128)      { g = Ah; grow = row0 + r; }                     \
            else if (r < 256) { g = Al; grow = row0 + r - 128; }               \
            else if (r < 512) { g = Wh; grow = col0 + r - 256; }               \
            else              { g = Wl; grow = col0 + r - 512; }               \
            cpasync16(sb + (uint32_t)((r * TLD + cq) * 2),                     \
                      g + (size_t)grow * GK + (kbase) + cq);                   \
        }                                                                      \
    } while (0)

    COPY_STAGE(0, 0);
    asm volatile("cp.async.commit_group;");

    const int NITER = GK / 32;     // 32
    for (int it = 0; it < NITER; it++) {
        asm volatile("cp.async.wait_group 0;");
        __syncthreads();
        if (it + 1 < NITER) COPY_STAGE((it + 1) & 1, (it + 1) * 32);
        asm volatile("cp.async.commit_group;");

        const uint32_t sb = sm32 + (uint32_t)((it & 1) * STAGE_BYTES);
        #pragma unroll
        for (int kk = 0; kk < 32; kk += 16) {
            const uint32_t kb = (uint32_t)(kk * 2);
            uint32_t bh[4][4], bl[4][4];
            #pragma unroll
            for (int p = 0; p < 4; p++) {
                uint32_t ba = sb + (uint32_t)(OFF_WH * 2) + boff
                            + (uint32_t)(p * 16 * TLD * 2) + kb;
                ldsm_x4(bh[p], ba);
                ldsm_x4(bl[p], ba + (uint32_t)((OFF_WL - OFF_WH) * 2));
            }
            #pragma unroll
            for (int ms = 0; ms < 4; ms++) {
                uint32_t aa = sb + aoff + (uint32_t)(ms * 16 * TLD * 2) + kb;
                uint32_t ah[4], al[4];
                ldsm_x4(ah, aa);
                ldsm_x4(al, aa + (uint32_t)(OFF_AL * 2));
                #pragma unroll
                for (int ns = 0; ns < 8; ns++) {
                    const uint32_t* bhp = &bh[ns >> 1][(ns & 1) * 2];
                    const uint32_t* blp = &bl[ns >> 1][(ns & 1) * 2];
                    mma_bf16(acc[ms][ns], ah, bhp);
                    mma_bf16(acc[ms][ns], ah, blp);
                    mma_bf16(acc[ms][ns], al, bhp);
                }
            }
        }
    }

    #pragma unroll
    for (int ms = 0; ms < 4; ms++) {
        int r = row0 + wm * 64 + ms * 16 + lr;
        float m0 = mask ? (float)mask[r]     : 1.0f;
        float m1 = mask ? (float)mask[r + 8] : 1.0f;
        #pragma unroll
        for (int ns = 0; ns < 8; ns++) {
            int c = col0 + wn * 64 + ns * 8 + lq;
            float b0 = bias[c], b1 = bias[c + 1];
            float2 o0 = make_float2(m0 * (acc[ms][ns][0] + b0),
                                    m0 * (acc[ms][ns][1] + b1));
            float2 o1 = make_float2(m1 * (acc[ms][ns][2] + b0),
                                    m1 * (acc[ms][ns][3] + b1));
            *(float2*)(C + (size_t)r * E_ + c)       = o0;
            *(float2*)(C + (size_t)(r + 8) * E_ + c) = o1;
        }
    }
}

// ---------------------------------------------------------------------------
// K2a: per-(b,t,e) tile sums of vm along S, TS2=32 (131K threads, 4x R13).
// ---------------------------------------------------------------------------
__global__ __launch_bounds__(256)
void tilesum_kernel(const float* __restrict__ vm, float* __restrict__ tsum)
{
    int e = blockIdx.x * 256 + threadIdx.x;
    int t = blockIdx.y;
    int b = blockIdx.z;
    const float* src = vm + ((size_t)b * S_ + (size_t)t * TS2) * E_ + e;
    float acc = 0.0f;
    #pragma unroll
    for (int s = 0; s < TS2; s++)
        acc += src[(size_t)s * E_];
    tsum[((size_t)b * NT2 + t) * E_ + e] = acc;
}

// ---------------------------------------------------------------------------
// K3: cross-tile fwd/bwd offsets (NT2=64). Two passes, no big reg array.
// ---------------------------------------------------------------------------
__global__ __launch_bounds__(256)
void scan_tiles_kernel(const float* __restrict__ tsum,
                       float* __restrict__ toff_f, float* __restrict__ toff_b)
{
    int e = blockIdx.x * 256 + threadIdx.x;
    int b = blockIdx.y;
    float acc = 0.0f;
    #pragma unroll 8
    for (int t = 0; t < NT2; t++) {
        size_t idx = ((size_t)b * NT2 + t) * E_ + e;
        toff_f[idx] = acc;
        acc += tsum[idx];
    }
    acc = 0.0f;
    #pragma unroll 8
    for (int t = NT2 - 1; t >= 0; t--) {
        size_t idx = ((size_t)b * NT2 + t) * E_ + e;
        acc += tsum[idx];
        toff_b[idx] = acc - tsum[idx] + tsum[idx]; // inclusive-from-t
    }
    // NOTE: toff_b[t] holds sum over tiles >= t (inclusive); combine uses
    // suf = toff_b[t] - acc_local_exclusive ... see scan_combine_kernel.
}

// ---------------------------------------------------------------------------
// K_w: per-(b,h,i) weights, Z in XLA:GPU row-reduce order (R7-validated —
// do not touch).
// ---------------------------------------------------------------------------
__device__ __forceinline__ float wval(int j, int i, int odd,
                                      float c0, float c1, float c2)
{
    if (j >= i) return c0;
    if (odd && j == i - 1) return c1;
    return c2;
}

__global__ __launch_bounds__(256)
void weights_kernel(const float* __restrict__ hier, float4* __restrict__ wts)
{
    int i = blockIdx.x * 256 + threadIdx.x;
    int h = blockIdx.y;
    int b = blockIdx.z;
    const float* hp = hier + ((size_t)b * H_ + h) * 3;
    float c0 = hp[0];
    float c1 = __fmul_rn(0.5f,  hp[1]);
    float c2 = __fmul_rn(0.25f, hp[2]);
    int odd = i & 1;

    float r[32];
    #pragma unroll 1
    for (int w = 0; w < 32; w++) {
        int jlo = w << 6;
        int jhi = jlo + 63;
        if (jlo >= i) {
            r[w] = __fmul_rn(64.0f, c0);
        } else if (jhi < i && !(odd && (i - 1) <= jhi)) {
            r[w] = __fmul_rn(64.0f, c2);
        } else {
            float p[32];
            #pragma unroll
            for (int t = 0; t < 32; t++) {
                int j = jlo + 2 * t;
                p[t] = __fadd_rn(wval(j, i, odd, c0, c1, c2),
                                 wval(j + 1, i, odd, c0, c1, c2));
            }
            #pragma unroll
            for (int s = 16; s > 0; s >>= 1)
                #pragma unroll
                for (int l = 0; l < 16; l++)
                    if (l < s) p[l] = __fadd_rn(p[l], p[l + s]);
            r[w] = p[0];
        }
    }
    #pragma unroll
    for (int s = 16; s > 0; s >>= 1)
        #pragma unroll
        for (int l = 0; l < 16; l++)
            if (l < s) r[l] = __fadd_rn(r[l], r[l + s]);

    float Z = __fadd_rn(r[0], 1e-8f);
    float4 o;
    o.x = __fdiv_rn(c0, Z);
    o.y = __fdiv_rn(c1, Z);
    o.z = __fdiv_rn(c2, Z);
    o.w = 0.0f;
    wts[((size_t)b * H_ + h) * S_ + i] = o;
}

// ---------------------------------------------------------------------------
// K4: fused local-scan + combine, TS2=32 per block-tile:
//   acc  = exclusive in-tile prefix of vm
//   pre  = toff_f[t] + acc
//   suf  = toff_b[t] - acc        (toff_b inclusive of tile t)
//   edge = vprev when i odd (i = 32t+s, so s odd; in-tile, s>=1)
//   att  = w0*suf + w1*edge + w2*(pre-edge) -> bf16 hi/lo split
// ---------------------------------------------------------------------------
__global__ __launch_bounds__(256)
void scan_combine_kernel(const float* __restrict__ vm,
                         const float* __restrict__ toff_f,
                         const float* __restrict__ toff_b,
                         const float4* __restrict__ wts,
                         __nv_bfloat16* __restrict__ atth,
                         __nv_bfloat16* __restrict__ attl)
{
    int e = blockIdx.x * 256 + threadIdx.x;
    int t = blockIdx.y;
    int b = blockIdx.z;
    int h = e >> 6;                                  // dh = 64
    size_t tidx = ((size_t)b * NT2 + t) * E_ + e;
    float offf = toff_f[tidx];
    float offb = toff_b[tidx];
    const float4* wp = wts + ((size_t)b * H_ + h) * S_ + (size_t)t * TS2;

    size_t cbase = ((size_t)b * S_ + (size_t)t * TS2) * E_ + e;
    const float* src = vm + cbase;
    __nv_bfloat16* dh = atth + cbase;
    __nv_bfloat16* dl = attl + cbase;

    float acc = 0.0f, vprev = 0.0f;
    #pragma unroll
    for (int s = 0; s < TS2; s++) {
        float v = src[(size_t)s * E_];
        float p  = offf + acc;
        float sf = offb - acc;
        float4 ww = wp[s];
        float edge = (s & 1) ? vprev : 0.0f;
        float val = ww.x * sf + ww.y * edge + ww.z * (p - edge);
        __nv_bfloat16 hi, lo;
        split_bf16(val, hi, lo);
        dh[(size_t)s * E_] = hi;
        dl[(size_t)s * E_] = lo;
        acc += v;
        vprev = v;
    }
}

// ---------------------------------------------------------------------------
// Launch. Inputs (metadata order):
// 0:x 1:attention_mask 2:level_indices(unused) 3:Wq 4:bq 5:Wk 6:bk
// 7:Wv 8:bv 9:hier 10:Wo 11:bo
// ---------------------------------------------------------------------------
extern "C" void kernel_launch(void* const* d_in, const int* in_sizes, int n_in,
                              void* d_out, int out_size)
{
    const float* x    = (const float*)d_in[0];
    const int*   am   = (const int*)  d_in[1];
    const float* Wv   = (const float*)d_in[7];
    const float* bv   = (const float*)d_in[8];
    const float* hier = (const float*)d_in[9];
    const float* Wo   = (const float*)d_in[10];
    const float* bo   = (const float*)d_in[11];
    float* out = (float*)d_out;

    float *vm, *tsum, *toff_f, *toff_b;
    float4* wts;
    __nv_bfloat16 *xh, *xl, *ath, *atl, *wvh, *wvl, *woh, *wol;
    cudaGetSymbolAddress((void**)&vm,     g_vm);
    cudaGetSymbolAddress((void**)&tsum,   g_tsum);
    cudaGetSymbolAddress((void**)&toff_f, g_tofff);
    cudaGetSymbolAddress((void**)&toff_b, g_toffb);
    cudaGetSymbolAddress((void**)&wts,    g_wts);
    cudaGetSymbolAddress((void**)&xh,     g_xh);
    cudaGetSymbolAddress((void**)&xl,     g_xl);
    cudaGetSymbolAddress((void**)&ath,    g_ath);
    cudaGetSymbolAddress((void**)&atl,    g_atl);
    cudaGetSymbolAddress((void**)&wvh,    g_wvh);
    cudaGetSymbolAddress((void**)&wvl,    g_wvl);
    cudaGetSymbolAddress((void**)&woh,    g_woh);
    cudaGetSymbolAddress((void**)&wol,    g_wol);

    static int smem_set = 0;
    if (!smem_set) {
        cudaFuncSetAttribute(gemm_split_kernel,
                             cudaFuncAttributeMaxDynamicSharedMemorySize,
                             GSMEM_BYTES);
        smem_set = 1;
    }

    // Split prep: x, Wv, Wo -> bf16 hi/lo
    split_kernel<<<(M_ * E_ / 4 + 255) / 256, 256>>>(x,  xh,  xl,  M_ * E_ / 4);
    split_kernel<<<(E_ * E_ / 4 + 255) / 256, 256>>>(Wv, wvh, wvl, E_ * E_ / 4);
    split_kernel<<<(E_ * E_ / 4 + 255) / 256, 256>>>(Wo, woh, wol, E_ * E_ / 4);

    dim3 gemm_grid(E_ / 256, M_ / 128);   // (4, 32) = 128 CTAs

    // K1: vm = mask * (x @ Wv^T + bv)
    gemm_split_kernel<<<gemm_grid, 256, GSMEM_BYTES>>>(xh, xl, wvh, wvl, bv, am, vm);

    // K_w: weights with XLA-tree Z
    weights_kernel<<<dim3(S_ / 256, H_, B_), 256>>>(hier, wts);

    // K2a/K3: tile sums (TS=32) + cross-tile offsets
    tilesum_kernel<<<dim3(E_ / 256, NT2, B_), 256>>>(vm, tsum);
    scan_tiles_kernel<<<dim3(E_ / 256, B_), 256>>>(tsum, toff_f, toff_b);

    // K4: fused scan+combine -> att (bf16 hi/lo)
    scan_combine_kernel<<<dim3(E_ / 256, NT2, B_), 256>>>(vm, toff_f, toff_b,
                                                          wts, ath, atl);

    // K5: out = att @ Wo^T + bo
    gemm_split_kernel<<<gemm_grid, 256, GSMEM_BYTES>>>(ath, atl, woh, wol, bo,
                                                       nullptr, out);
}